// round 1
// baseline (speedup 1.0000x reference)
#include <cuda_runtime.h>
#include <math.h>

#define TLEN 2048
#define BATCH 64
#define HID 50
#define G3 150
#define GP 160      // padded gate columns (3H=150 -> 160)
#define DIN0 128

// scratch (device globals: allocation-free rule)
__device__ float g_buf0[TLEN*BATCH*HID];
__device__ float g_buf1[TLEN*BATCH*HID];
__device__ float g_h1[BATCH*1600];

__device__ __forceinline__ float sigmoidf_fast(float x){
    return __fdividef(1.0f, 1.0f + __expf(-x));
}
__device__ __forceinline__ float tanhf_fast(float x){
    float e = __expf(2.0f*x);              // inf-safe: x>>0 -> 1, x<<0 -> -1
    return 1.0f - __fdividef(2.0f, e + 1.0f);
}

// One warp owns S independent dilated-GRU sequences; h kept in smem, W/U in smem.
// Lane j-mapping over padded 160 gate cols: u<4 -> jp=lane*4+u (float4 loads),
// u==4 -> jp=128+lane. Gate roles resolved after an smem round-trip.
template<int D_IN, int S, int WARPS, bool FIRST>
__global__ void __launch_bounds__(WARPS*32, 1)
gru_scan_kernel(const float* __restrict__ xin,
                const float* __restrict__ W,
                const float* __restrict__ U,
                const float* __restrict__ bvec,
                float* __restrict__ out,
                int rate, int dn)
{
    extern __shared__ float sm[];
    float* Wp = sm;                       // D_IN * GP
    float* Up = Wp + D_IN*GP;             // HID  * GP
    float* pool = Up + HID*GP;
    const int PER_WARP = S*(D_IN + 64 + GP + GP);

    int tid  = threadIdx.x;
    int wid  = tid >> 5;
    int lane = tid & 31;

    float* x_sh  = pool + wid*PER_WARP;   // S * D_IN
    float* h_sh  = x_sh + S*D_IN;         // S * 64
    float* gx_sh = h_sh + S*64;           // S * GP
    float* gr_sh = gx_sh + S*GP;          // S * GP

    for (int idx = tid; idx < D_IN*GP; idx += WARPS*32){
        int k = idx / GP, jp = idx % GP;
        Wp[idx] = (jp < G3) ? W[k*G3 + jp] : 0.0f;
    }
    for (int idx = tid; idx < HID*GP; idx += WARPS*32){
        int k = idx / GP, jp = idx % GP;
        Up[idx] = (jp < G3) ? U[k*G3 + jp] : 0.0f;
    }
    float bi[5], br[5];
    #pragma unroll
    for (int u=0; u<5; u++){
        int jp = (u<4) ? (lane*4+u) : (128+lane);
        bi[u] = (jp < G3) ? bvec[jp]      : 0.0f;
        br[u] = (jp < G3) ? bvec[G3 + jp] : 0.0f;
    }
    #pragma unroll
    for (int s=0; s<S; s++)
        for (int k=lane; k<64; k+=32) h_sh[s*64+k] = 0.0f;
    __syncthreads();

    int q0 = (blockIdx.x*WARPS + wid)*S;  // S consecutive sequences, same residue rr
    int b0 = q0 & 63;
    int rr = q0 >> 6;

    for (int st=0; st<dn; st++){
        int t_in = st*rate + rr;
        // stage inputs
        #pragma unroll
        for (int s=0; s<S; s++){
            const float* src = FIRST
                ? (xin + (size_t)(b0+s)*TLEN*DIN0 + (size_t)t_in*DIN0)
                : (xin + (size_t)t_in*BATCH*HID + (size_t)(b0+s)*HID);
            for (int k=lane; k<D_IN; k+=32) x_sh[s*D_IN+k] = __ldg(src+k);
        }
        float accx[S][5], accr[S][5];
        #pragma unroll
        for (int s=0; s<S; s++){
            #pragma unroll
            for (int u=0; u<5; u++){ accx[s][u] = bi[u]; accr[s][u] = br[u]; }
        }
        __syncwarp();

        // input transform: accx += x @ W
        #pragma unroll 2
        for (int k=0; k<D_IN; k++){
            float4 w4 = *(const float4*)(Wp + k*GP + lane*4);
            float  w5 = Wp[k*GP + 128 + lane];
            #pragma unroll
            for (int s=0; s<S; s++){
                float xv = x_sh[s*D_IN + k];
                accx[s][0] += xv*w4.x; accx[s][1] += xv*w4.y;
                accx[s][2] += xv*w4.z; accx[s][3] += xv*w4.w;
                accx[s][4] += xv*w5;
            }
        }
        // recurrent: accr += h @ U
        #pragma unroll 2
        for (int k=0; k<HID; k++){
            float4 u4 = *(const float4*)(Up + k*GP + lane*4);
            float  u5 = Up[k*GP + 128 + lane];
            #pragma unroll
            for (int s=0; s<S; s++){
                float hv = h_sh[s*64 + k];
                accr[s][0] += hv*u4.x; accr[s][1] += hv*u4.y;
                accr[s][2] += hv*u4.z; accr[s][3] += hv*u4.w;
                accr[s][4] += hv*u5;
            }
        }
        // park gates in smem for role-based combine
        #pragma unroll
        for (int s=0; s<S; s++){
            *(float4*)(gx_sh + s*GP + lane*4) =
                make_float4(accx[s][0],accx[s][1],accx[s][2],accx[s][3]);
            gx_sh[s*GP + 128 + lane] = accx[s][4];
            *(float4*)(gr_sh + s*GP + lane*4) =
                make_float4(accr[s][0],accr[s][1],accr[s][2],accr[s][3]);
            gr_sh[s*GP + 128 + lane] = accr[s][4];
        }
        __syncwarp();

        int t_out = rr*dn + st;
        #pragma unroll
        for (int s=0; s<S; s++){
            float* gx = gx_sh + s*GP;
            float* gr = gr_sh + s*GP;
            for (int c=lane; c<HID; c+=32){
                float z  = sigmoidf_fast(gx[c]      + gr[c]);
                float r  = sigmoidf_fast(gx[50+c]   + gr[50+c]);
                float hh = tanhf_fast  (gx[100+c] + r*gr[100+c]);
                float hold = h_sh[s*64 + c];
                float hn = hh + z*(hold - hh);
                h_sh[s*64 + c] = hn;
                out[(size_t)t_out*BATCH*HID + (size_t)(b0+s)*HID + c] = hn;
            }
        }
        __syncwarp();
    }
}

// head: h1 = relu(feats @ W2 + b2); feats[b, it*50+j] = Xf[2016+it, b, j]
__global__ void __launch_bounds__(256,1)
dense2_kernel(const float* __restrict__ Xf, const float* __restrict__ W2,
              const float* __restrict__ b2, float* __restrict__ h1)
{
    __shared__ float As[64][65];
    __shared__ float Bs[64][65];
    int tid = threadIdx.x;
    int n0 = blockIdx.x*64;
    int tm = tid/16, tn = tid%16;
    float acc[4][4] = {};
    for (int kc=0; kc<1600; kc+=64){
        for (int p=tid; p<64*64; p+=256){
            int m = p/64, kk = p%64;
            int i = kc + kk;
            As[m][kk] = Xf[(size_t)(2016 + i/50)*(BATCH*HID) + m*HID + (i%50)];
        }
        for (int p=tid; p<64*64; p+=256){
            int kk = p/64, n = p%64;
            Bs[kk][n] = W2[(size_t)(kc+kk)*1600 + n0 + n];
        }
        __syncthreads();
        #pragma unroll 8
        for (int kk=0; kk<64; kk++){
            float a[4], bb[4];
            #pragma unroll
            for (int i=0;i<4;i++) a[i]  = As[tm*4+i][kk];
            #pragma unroll
            for (int j=0;j<4;j++) bb[j] = Bs[kk][tn*4+j];
            #pragma unroll
            for (int i=0;i<4;i++)
                #pragma unroll
                for (int j=0;j<4;j++) acc[i][j] += a[i]*bb[j];
        }
        __syncthreads();
    }
    #pragma unroll
    for (int i=0;i<4;i++){
        int m = tm*4+i;
        #pragma unroll
        for (int j=0;j<4;j++){
            int n = n0 + tn*4 + j;
            float v = acc[i][j] + b2[n];
            h1[(size_t)m*1600 + n] = fmaxf(v, 0.0f);
        }
    }
}

__global__ void __launch_bounds__(64,1)
cls_softmax_kernel(const float* __restrict__ h1, const float* __restrict__ Wc,
                   const float* __restrict__ bc, float* __restrict__ out)
{
    __shared__ float hs[1600];
    __shared__ float lg[41];
    __shared__ float red[2];
    int b = blockIdx.x, tid = threadIdx.x;
    for (int i=tid; i<1600; i+=64) hs[i] = h1[(size_t)b*1600 + i];
    __syncthreads();
    if (tid < 41){
        float a0=0.f, a1=0.f, a2=0.f, a3=0.f;
        for (int i=0; i<1600; i+=4){
            a0 += hs[i+0]*Wc[(size_t)(i+0)*41 + tid];
            a1 += hs[i+1]*Wc[(size_t)(i+1)*41 + tid];
            a2 += hs[i+2]*Wc[(size_t)(i+2)*41 + tid];
            a3 += hs[i+3]*Wc[(size_t)(i+3)*41 + tid];
        }
        lg[tid] = (a0+a1) + (a2+a3) + bc[tid];
    }
    __syncthreads();
    if (tid == 0){
        float mx = lg[0];
        for (int o=1;o<41;o++) mx = fmaxf(mx, lg[o]);
        float sum = 0.f;
        for (int o=0;o<41;o++) sum += expf(lg[o]-mx);
        red[0]=mx; red[1]=sum;
    }
    __syncthreads();
    if (tid < 41) out[(size_t)b*41 + tid] = expf(lg[tid]-red[0]) / red[1];
}

static const int SMEM_L0 = (DIN0*GP + HID*GP + 8*4*(DIN0+64+GP+GP))*4; // 179456 B
static const int SMEM_LX = (HID*GP  + HID*GP + 8*4*(HID +64+GP+GP))*4; // 119552 B

extern "C" void kernel_launch(void* const* d_in, const int* in_sizes, int n_in,
                              void* d_out, int out_size)
{
    const float* x   = (const float*)d_in[0];
    const float* W0  = (const float*)d_in[1];
    const float* U0  = (const float*)d_in[2];
    const float* b0v = (const float*)d_in[3];
    const float* Ws  = (const float*)d_in[4];   // [5][50][150]
    const float* Us  = (const float*)d_in[5];
    const float* bs  = (const float*)d_in[6];   // [5][2][150]
    const float* W2  = (const float*)d_in[7];
    const float* b2  = (const float*)d_in[8];
    const float* Wc  = (const float*)d_in[9];
    const float* bc  = (const float*)d_in[10];
    float* out = (float*)d_out;

    float *buf0, *buf1, *h1p;
    cudaGetSymbolAddress((void**)&buf0, g_buf0);
    cudaGetSymbolAddress((void**)&buf1, g_buf1);
    cudaGetSymbolAddress((void**)&h1p,  g_h1);

    cudaFuncSetAttribute(gru_scan_kernel<DIN0,4,8,true>,
                         cudaFuncAttributeMaxDynamicSharedMemorySize, SMEM_L0);
    cudaFuncSetAttribute(gru_scan_kernel<HID,4,8,false>,
                         cudaFuncAttributeMaxDynamicSharedMemorySize, SMEM_LX);

    // layer 0: rate 32, dn 64, 2048 sequences, 32 seq/CTA -> 64 CTAs
    gru_scan_kernel<DIN0,4,8,true><<<64, 256, SMEM_L0>>>(x, W0, U0, b0v, buf0, 32, 64);

    const int rates[5] = {64,128,256,512,1024};
    float* bufs[2] = {buf0, buf1};
    for (int i=0; i<5; i++){
        int rate = rates[i];
        int dn   = TLEN / rate;
        int grid = (rate*BATCH) / 32;
        gru_scan_kernel<HID,4,8,false><<<grid, 256, SMEM_LX>>>(
            bufs[i&1], Ws + (size_t)i*HID*G3, Us + (size_t)i*HID*G3,
            bs + (size_t)i*2*G3, bufs[(i+1)&1], rate, dn);
    }
    // final output is in buf1 (layer 5 writes bufs[(4+1)&1] = buf1)
    dense2_kernel<<<25, 256>>>(buf1, W2, b2, h1p);
    cls_softmax_kernel<<<64, 64>>>(h1p, Wc, bc, out);
}

// round 2
// speedup vs baseline: 1.6297x; 1.6297x over previous
#include <cuda_runtime.h>
#include <math.h>

#define TLEN 2048
#define BATCH 64
#define HID 50
#define G3 150
#define WS 192      // weight smem row stride (3 roles * 64 paired floats)
#define XGS 152     // xg row stride
#define DIN0 128

// scratch (device globals: allocation-free rule)
__device__ float g_buf0[TLEN*BATCH*HID];
__device__ float g_buf1[TLEN*BATCH*HID];
__device__ float g_xg[TLEN*BATCH*XGS];
__device__ float g_h1[BATCH*1600];

__device__ __forceinline__ float sigf(float x){
    return __fdividef(1.0f, 1.0f + __expf(-x));
}
__device__ __forceinline__ float tanhf_fast(float x){
    float e = __expf(2.0f*x);              // inf-safe
    return 1.0f - __fdividef(2.0f, e + 1.0f);
}

// ---------------------------------------------------------------------------
// Layer-0 input-gate GEMM: xg[t*64+b][col] = x[b,t,:] @ W0[:,col] + bi[col]
// grid.x = TLEN (one timestep per CTA: 64 batch rows x 150 cols, K=128)
// ---------------------------------------------------------------------------
__global__ void __launch_bounds__(256,2)
xg_gemm_kernel(const float* __restrict__ x, const float* __restrict__ W,
               const float* __restrict__ bi, float* __restrict__ xg)
{
    extern __shared__ float sm[];
    float* Xs = sm;              // 64 x 132 (padded)
    float* Wk = sm + 64*132;     // 32 x 160
    int t = blockIdx.x;
    int tid = threadIdx.x;
    int tm = tid >> 3;           // 0..31 -> slots 2tm, 2tm+1
    int tn = tid & 7;            // cols 20*tn .. 20*tn+19

    for (int p = tid; p < 64*DIN0; p += 256){
        int b = p >> 7, d = p & 127;
        Xs[b*132 + d] = x[(size_t)b*TLEN*DIN0 + (size_t)t*DIN0 + d];
    }
    float acc[2][20];
    #pragma unroll
    for (int i=0;i<2;i++)
        #pragma unroll
        for (int j=0;j<20;j++) acc[i][j]=0.f;

    for (int kc = 0; kc < DIN0; kc += 32){
        __syncthreads();
        for (int p = tid; p < 32*160; p += 256){
            int r = p/160, c = p - r*160;
            Wk[p] = (c < G3) ? W[(size_t)(kc+r)*G3 + c] : 0.f;
        }
        __syncthreads();
        #pragma unroll 4
        for (int kk = 0; kk < 32; kk++){
            float a0 = Xs[(2*tm)  *132 + kc+kk];
            float a1 = Xs[(2*tm+1)*132 + kc+kk];
            const float4* bp = (const float4*)(Wk + kk*160 + tn*20);
            float bb[20];
            #pragma unroll
            for (int q=0;q<5;q++){
                float4 v = bp[q];
                bb[4*q]=v.x; bb[4*q+1]=v.y; bb[4*q+2]=v.z; bb[4*q+3]=v.w;
            }
            #pragma unroll
            for (int j=0;j<20;j++){ acc[0][j] += a0*bb[j]; acc[1][j] += a1*bb[j]; }
        }
    }
    #pragma unroll
    for (int i=0;i<2;i++){
        int b = 2*tm+i;
        size_t base = ((size_t)t*64 + b)*XGS;
        #pragma unroll
        for (int j=0;j<20;j++){
            int col = tn*20 + j;
            if (col < G3) xg[base + col] = acc[i][j] + bi[col];
        }
    }
}

// ---------------------------------------------------------------------------
// Fused dilated-GRU scan. Lane owns channels c1=lane, c2=lane+32 (<50).
// Gate accumulation fully in registers; weights as paired float2 in smem.
// PRE=true: input gates precomputed (xg, stride XGS); else fused x@W.
// ---------------------------------------------------------------------------
template<int S, int WARPS, bool PRE>
__global__ void __launch_bounds__(WARPS*32, 2)
scan_kernel(const float* __restrict__ xin, const float* __restrict__ W,
            const float* __restrict__ U, const float* __restrict__ bvec,
            float* __restrict__ out, int rate, int dn)
{
    extern __shared__ float sm[];
    float* Up = sm;                              // 50*WS
    float* Wp = sm + 50*WS;                      // 50*WS (MODE0 only)
    float* pool = sm + (PRE ? 1 : 2)*50*WS;
    const int PW = PRE ? S*64 : S*(50+64);

    int tid = threadIdx.x, wid = tid>>5, lane = tid&31;
    float* x_sh = pool + wid*PW;                 // S*50 (MODE0)
    float* h_sh = PRE ? (pool + wid*PW) : (x_sh + S*50);

    // weights -> paired smem: row k, [role*64 + 2j] = M[k][role*50+j],
    //                         [role*64 + 2j+1] = (j+32<50)? M[k][role*50+j+32] : 0
    for (int idx = tid; idx < 50*WS; idx += WARPS*32){
        int k = idx / WS, rem = idx - k*WS;
        int role = rem >> 6, j2 = rem & 63;
        int j = (j2 >> 1) + 32*(j2 & 1);
        Up[idx] = (j < 50) ? U[k*G3 + role*50 + j] : 0.f;
    }
    if (!PRE){
        for (int idx = tid; idx < 50*WS; idx += WARPS*32){
            int k = idx / WS, rem = idx - k*WS;
            int role = rem >> 6, j2 = rem & 63;
            int j = (j2 >> 1) + 32*(j2 & 1);
            Wp[idx] = (j < 50) ? W[k*G3 + role*50 + j] : 0.f;
        }
    }

    const bool v2 = lane < 18;
    const int c1 = lane, c2 = lane + 32;
    const float* bi = bvec;
    const float* br = bvec + G3;
    float bz1, bz2, brr1, brr2, bhx1, bhx2, bhr1, bhr2;
    if (PRE){
        bz1 = br[c1]; brr1 = br[50+c1]; bhr1 = br[100+c1];
        bz2 = v2 ? br[c2] : 0.f; brr2 = v2 ? br[50+c2] : 0.f; bhr2 = v2 ? br[100+c2] : 0.f;
        bhx1 = 0.f; bhx2 = 0.f;
    } else {
        bz1 = bi[c1]+br[c1]; brr1 = bi[50+c1]+br[50+c1];
        bhx1 = bi[100+c1];   bhr1 = br[100+c1];
        bz2 = v2 ? bi[c2]+br[c2] : 0.f; brr2 = v2 ? bi[50+c2]+br[50+c2] : 0.f;
        bhx2 = v2 ? bi[100+c2] : 0.f;   bhr2 = v2 ? br[100+c2] : 0.f;
    }
    #pragma unroll
    for (int s=0;s<S;s++)
        for (int k=lane;k<64;k+=32) h_sh[s*64+k]=0.f;
    __syncthreads();

    int q0 = (blockIdx.x*WARPS + wid)*S;
    int b0 = q0 & 63, rr = q0 >> 6;

    // one-step-ahead register prefetch of inputs
    float xp1[S], xp2[S];
    float gz1[S],gz2[S],gr1[S],gr2[S],gh1[S],gh2[S];
    if (PRE){
        #pragma unroll
        for (int s=0;s<S;s++){
            size_t base = ((size_t)rr*64 + b0+s)*XGS;
            gz1[s]=xin[base+c1]; gr1[s]=xin[base+50+c1]; gh1[s]=xin[base+100+c1];
            gz2[s]= v2? xin[base+c2]:0.f; gr2[s]= v2? xin[base+50+c2]:0.f; gh2[s]= v2? xin[base+100+c2]:0.f;
        }
    } else {
        #pragma unroll
        for (int s=0;s<S;s++){
            const float* src = xin + ((size_t)rr*64 + b0+s)*HID;
            xp1[s]=src[c1]; xp2[s]= v2? src[c2]:0.f;
        }
    }

    for (int st=0; st<dn; st++){
        float az1[S],az2[S],ar1[S],ar2[S],ahx1[S],ahx2[S],ahr1[S],ahr2[S];
        if (!PRE){
            #pragma unroll
            for (int s=0;s<S;s++){
                x_sh[s*50+c1] = xp1[s];
                if (v2) x_sh[s*50+c2] = xp2[s];
            }
            __syncwarp();
            #pragma unroll
            for (int s=0;s<S;s++){
                az1[s]=bz1; az2[s]=bz2; ar1[s]=brr1; ar2[s]=brr2;
                ahx1[s]=bhx1; ahx2[s]=bhx2; ahr1[s]=bhr1; ahr2[s]=bhr2;
            }
        } else {
            #pragma unroll
            for (int s=0;s<S;s++){
                az1[s]=bz1+gz1[s]; az2[s]=bz2+gz2[s];
                ar1[s]=brr1+gr1[s]; ar2[s]=brr2+gr2[s];
                ahx1[s]=gh1[s]; ahx2[s]=gh2[s];
                ahr1[s]=bhr1; ahr2[s]=bhr2;
            }
        }
        if (st+1 < dn){
            int t_in = (st+1)*rate + rr;
            if (PRE){
                #pragma unroll
                for (int s=0;s<S;s++){
                    size_t base = ((size_t)t_in*64 + b0+s)*XGS;
                    gz1[s]=xin[base+c1]; gr1[s]=xin[base+50+c1]; gh1[s]=xin[base+100+c1];
                    gz2[s]= v2? xin[base+c2]:0.f; gr2[s]= v2? xin[base+50+c2]:0.f; gh2[s]= v2? xin[base+100+c2]:0.f;
                }
            } else {
                #pragma unroll
                for (int s=0;s<S;s++){
                    const float* src = xin + ((size_t)t_in*64 + b0+s)*HID;
                    xp1[s]=src[c1]; xp2[s]= v2? src[c2]:0.f;
                }
            }
        }
        if (!PRE){
            #pragma unroll 2
            for (int k=0;k<50;k++){
                const float2* wr2 = (const float2*)(Wp + k*WS);
                float2 vz = wr2[lane], vr = wr2[32+lane], vh = wr2[64+lane];
                #pragma unroll
                for (int s=0;s<S;s++){
                    float xv = x_sh[s*50+k];
                    az1[s]  += xv*vz.x; az2[s]  += xv*vz.y;
                    ar1[s]  += xv*vr.x; ar2[s]  += xv*vr.y;
                    ahx1[s] += xv*vh.x; ahx2[s] += xv*vh.y;
                }
            }
        }
        #pragma unroll 2
        for (int k=0;k<50;k++){
            const float2* ur2 = (const float2*)(Up + k*WS);
            float2 vz = ur2[lane], vr = ur2[32+lane], vh = ur2[64+lane];
            #pragma unroll
            for (int s=0;s<S;s++){
                float hv = h_sh[s*64+k];
                az1[s]  += hv*vz.x; az2[s]  += hv*vz.y;
                ar1[s]  += hv*vr.x; ar2[s]  += hv*vr.y;
                ahr1[s] += hv*vh.x; ahr2[s] += hv*vh.y;
            }
        }
        __syncwarp();
        int t_out = rr*dn + st;
        #pragma unroll
        for (int s=0;s<S;s++){
            float* op = out + ((size_t)t_out*64 + b0+s)*HID;
            float z  = sigf(az1[s]);
            float r  = sigf(ar1[s]);
            float hh = tanhf_fast(ahx1[s] + r*ahr1[s]);
            float hold = h_sh[s*64+c1];
            float hn = hh + z*(hold - hh);
            h_sh[s*64+c1] = hn; op[c1] = hn;
            if (v2){
                float z2v = sigf(az2[s]);
                float r2v = sigf(ar2[s]);
                float hh2 = tanhf_fast(ahx2[s] + r2v*ahr2[s]);
                float hold2 = h_sh[s*64+c2];
                float hn2 = hh2 + z2v*(hold2 - hh2);
                h_sh[s*64+c2] = hn2; op[c2] = hn2;
            }
        }
        __syncwarp();
    }
}

// ---------------------------------------------------------------------------
// head
// ---------------------------------------------------------------------------
__global__ void __launch_bounds__(256,1)
dense2_kernel(const float* __restrict__ Xf, const float* __restrict__ W2,
              const float* __restrict__ b2, float* __restrict__ h1)
{
    __shared__ float As[64][65];
    __shared__ float Bs[64][65];
    int tid = threadIdx.x;
    int n0 = blockIdx.x*64;
    int tm = tid/16, tn = tid%16;
    float acc[4][4] = {};
    for (int kc=0; kc<1600; kc+=64){
        for (int p=tid; p<64*64; p+=256){
            int m = p/64, kk = p%64;
            int i = kc + kk;
            As[m][kk] = Xf[(size_t)(2016 + i/50)*(BATCH*HID) + m*HID + (i%50)];
        }
        for (int p=tid; p<64*64; p+=256){
            int kk = p/64, n = p%64;
            Bs[kk][n] = W2[(size_t)(kc+kk)*1600 + n0 + n];
        }
        __syncthreads();
        #pragma unroll 8
        for (int kk=0; kk<64; kk++){
            float a[4], bb[4];
            #pragma unroll
            for (int i=0;i<4;i++) a[i]  = As[tm*4+i][kk];
            #pragma unroll
            for (int j=0;j<4;j++) bb[j] = Bs[kk][tn*4+j];
            #pragma unroll
            for (int i=0;i<4;i++)
                #pragma unroll
                for (int j=0;j<4;j++) acc[i][j] += a[i]*bb[j];
        }
        __syncthreads();
    }
    #pragma unroll
    for (int i=0;i<4;i++){
        int m = tm*4+i;
        #pragma unroll
        for (int j=0;j<4;j++){
            int n = n0 + tn*4 + j;
            float v = acc[i][j] + b2[n];
            h1[(size_t)m*1600 + n] = fmaxf(v, 0.0f);
        }
    }
}

__global__ void __launch_bounds__(64,1)
cls_softmax_kernel(const float* __restrict__ h1, const float* __restrict__ Wc,
                   const float* __restrict__ bc, float* __restrict__ out)
{
    __shared__ float hs[1600];
    __shared__ float lg[41];
    __shared__ float red[2];
    int b = blockIdx.x, tid = threadIdx.x;
    for (int i=tid; i<1600; i+=64) hs[i] = h1[(size_t)b*1600 + i];
    __syncthreads();
    if (tid < 41){
        float a0=0.f, a1=0.f, a2=0.f, a3=0.f;
        for (int i=0; i<1600; i+=4){
            a0 += hs[i+0]*Wc[(size_t)(i+0)*41 + tid];
            a1 += hs[i+1]*Wc[(size_t)(i+1)*41 + tid];
            a2 += hs[i+2]*Wc[(size_t)(i+2)*41 + tid];
            a3 += hs[i+3]*Wc[(size_t)(i+3)*41 + tid];
        }
        lg[tid] = (a0+a1) + (a2+a3) + bc[tid];
    }
    __syncthreads();
    if (tid == 0){
        float mx = lg[0];
        for (int o=1;o<41;o++) mx = fmaxf(mx, lg[o]);
        float sum = 0.f;
        for (int o=0;o<41;o++) sum += expf(lg[o]-mx);
        red[0]=mx; red[1]=sum;
    }
    __syncthreads();
    if (tid < 41) out[(size_t)b*41 + tid] = expf(lg[tid]-red[0]) / red[1];
}

// ---------------------------------------------------------------------------
static const int SM_GEMM  = (64*132 + 32*160)*4;          // 54272
static const int SM_PRE   = (50*WS + 4*4*64)*4;           // 42496
static const int SM_M0_W4 = (2*50*WS + 4*4*(50+64))*4;    // 84096
static const int SM_M0_W8 = (2*50*WS + 8*4*(50+64))*4;    // 91392

extern "C" void kernel_launch(void* const* d_in, const int* in_sizes, int n_in,
                              void* d_out, int out_size)
{
    const float* x   = (const float*)d_in[0];
    const float* W0  = (const float*)d_in[1];
    const float* U0  = (const float*)d_in[2];
    const float* b0v = (const float*)d_in[3];
    const float* Ws  = (const float*)d_in[4];   // [5][50][150]
    const float* Us  = (const float*)d_in[5];
    const float* bs  = (const float*)d_in[6];   // [5][2][150]
    const float* W2  = (const float*)d_in[7];
    const float* b2  = (const float*)d_in[8];
    const float* Wc  = (const float*)d_in[9];
    const float* bc  = (const float*)d_in[10];
    float* out = (float*)d_out;

    float *buf0, *buf1, *xg, *h1p;
    cudaGetSymbolAddress((void**)&buf0, g_buf0);
    cudaGetSymbolAddress((void**)&buf1, g_buf1);
    cudaGetSymbolAddress((void**)&xg,   g_xg);
    cudaGetSymbolAddress((void**)&h1p,  g_h1);

    cudaFuncSetAttribute(xg_gemm_kernel,
                         cudaFuncAttributeMaxDynamicSharedMemorySize, SM_GEMM);
    cudaFuncSetAttribute(scan_kernel<4,4,true>,
                         cudaFuncAttributeMaxDynamicSharedMemorySize, SM_PRE);
    cudaFuncSetAttribute(scan_kernel<4,4,false>,
                         cudaFuncAttributeMaxDynamicSharedMemorySize, SM_M0_W4);
    cudaFuncSetAttribute(scan_kernel<4,8,false>,
                         cudaFuncAttributeMaxDynamicSharedMemorySize, SM_M0_W8);

    // layer 0: full-chip input GEMM, then recurrent-only scan (2048 seqs)
    xg_gemm_kernel<<<2048, 256, SM_GEMM>>>(x, W0, b0v, xg);
    scan_kernel<4,4,true><<<128, 128, SM_PRE>>>(xg, nullptr, U0, b0v, buf0, 32, 64);

    // layer 1 (rate 64): 4096 seqs, 16/CTA -> 256 CTAs
    scan_kernel<4,4,false><<<256, 128, SM_M0_W4>>>(
        buf0, Ws + 0*HID*G3, Us + 0*HID*G3, bs + 0*2*G3, buf1, 64, 32);
    // layers 2-5: 32 seqs/CTA
    scan_kernel<4,8,false><<<256, 256, SM_M0_W8>>>(
        buf1, Ws + 1*HID*G3, Us + 1*HID*G3, bs + 1*2*G3, buf0, 128, 16);
    scan_kernel<4,8,false><<<512, 256, SM_M0_W8>>>(
        buf0, Ws + 2*HID*G3, Us + 2*HID*G3, bs + 2*2*G3, buf1, 256, 8);
    scan_kernel<4,8,false><<<1024, 256, SM_M0_W8>>>(
        buf1, Ws + 3*HID*G3, Us + 3*HID*G3, bs + 3*2*G3, buf0, 512, 4);
    scan_kernel<4,8,false><<<2048, 256, SM_M0_W8>>>(
        buf0, Ws + 4*HID*G3, Us + 4*HID*G3, bs + 4*2*G3, buf1, 1024, 2);

    dense2_kernel<<<25, 256>>>(buf1, W2, b2, h1p);
    cls_softmax_kernel<<<64, 64>>>(h1p, Wc, bc, out);
}